// round 2
// baseline (speedup 1.0000x reference)
#include <cuda_runtime.h>
#include <cuda_bf16.h>
#include <cstdint>

// Problem constants
#define Bsz 8
#define SEQ 1024
#define HID 512
#define NHEAD 8
#define HDIM 64
#define BH (Bsz*NHEAD)          // 64
#define ROWS (Bsz*SEQ)          // 8192

// Scratch for Q/K/V in [B, NH, S, HD] layout
__device__ float g_q[BH * SEQ * HDIM];
__device__ float g_k[BH * SEQ * HDIM];
__device__ float g_v[BH * SEQ * HDIM];

// ---------------------------------------------------------------------------
// Fused QKV projection: C[i, j] = sum_k X[i,k] * W[j,k] + b[j]
// j in [0,1536): 0-511 -> Q (Wq), 512-1023 -> K, 1024-1535 -> V.
// Output written directly in [B, NH, S, HD] layout.
// Tile: 64x64 output per block, BK=32, 256 threads, 4x4 per thread.
// ---------------------------------------------------------------------------
#define QKV_BM 64
#define QKV_BN 64
#define QKV_BK 32

__global__ __launch_bounds__(256) void qkv_kernel(
    const float* __restrict__ X,
    const float* __restrict__ Wq, const float* __restrict__ bq,
    const float* __restrict__ Wk, const float* __restrict__ bk,
    const float* __restrict__ Wv, const float* __restrict__ bv)
{
    __shared__ float Xs[QKV_BM][QKV_BK + 1];
    __shared__ float Ws[QKV_BN][QKV_BK + 1];

    const int ib = blockIdx.x;           // 0..127 : row tile (64 rows)
    const int jb = blockIdx.y;           // 0..23  : col tile (64 cols)
    const int jsel = jb >> 3;            // 0=Q, 1=K, 2=V
    const int h = jb & 7;                // head (64 cols == one head)

    const float* W = (jsel == 0) ? Wq : (jsel == 1) ? Wk : Wv;
    const float* bias = (jsel == 0) ? bq : (jsel == 1) ? bk : bv;
    float* outp = (jsel == 0) ? g_q : (jsel == 1) ? g_k : g_v;

    const int tid = threadIdx.x;
    const int tx = tid & 15;
    const int ty = tid >> 4;
    const int row0 = ib * QKV_BM;
    const int col0 = h * 64;             // column offset within the 512-wide weight

    float acc[4][4];
#pragma unroll
    for (int i = 0; i < 4; i++)
#pragma unroll
        for (int j = 0; j < 4; j++) acc[i][j] = 0.f;

    for (int kb = 0; kb < HID; kb += QKV_BK) {
        // Load X tile 64x32 (512 float4, 2 per thread)
#pragma unroll
        for (int t = tid; t < QKV_BM * QKV_BK / 4; t += 256) {
            int r = t >> 3, c4 = (t & 7) * 4;
            float4 v4 = *(const float4*)&X[(size_t)(row0 + r) * HID + kb + c4];
            Xs[r][c4 + 0] = v4.x; Xs[r][c4 + 1] = v4.y;
            Xs[r][c4 + 2] = v4.z; Xs[r][c4 + 3] = v4.w;
        }
        // Load W tile 64x32
#pragma unroll
        for (int t = tid; t < QKV_BN * QKV_BK / 4; t += 256) {
            int r = t >> 3, c4 = (t & 7) * 4;
            float4 v4 = *(const float4*)&W[(size_t)(col0 + r) * HID + kb + c4];
            Ws[r][c4 + 0] = v4.x; Ws[r][c4 + 1] = v4.y;
            Ws[r][c4 + 2] = v4.z; Ws[r][c4 + 3] = v4.w;
        }
        __syncthreads();

#pragma unroll
        for (int kk = 0; kk < QKV_BK; kk++) {
            float x[4], w[4];
#pragma unroll
            for (int i = 0; i < 4; i++) x[i] = Xs[ty + 16 * i][kk];
#pragma unroll
            for (int j = 0; j < 4; j++) w[j] = Ws[tx + 16 * j][kk];
#pragma unroll
            for (int i = 0; i < 4; i++)
#pragma unroll
                for (int j = 0; j < 4; j++) acc[i][j] = fmaf(x[i], w[j], acc[i][j]);
        }
        __syncthreads();
    }

    // Write in [B, NH, S, HD] layout, add bias
#pragma unroll
    for (int i = 0; i < 4; i++) {
        int grow = row0 + ty + 16 * i;
        int b = grow >> 10;
        int s = grow & 1023;
        size_t base = ((size_t)(b * NHEAD + h) * SEQ + s) * HDIM;
#pragma unroll
        for (int j = 0; j < 4; j++) {
            int d = tx + 16 * j;
            outp[base + d] = acc[i][j] + bias[col0 + d];
        }
    }
}

// ---------------------------------------------------------------------------
// Flash-style attention. One block per (q-tile of 64 rows, b*NH+h).
// 256 threads, 4x4 register micro-tiles for both QK^T and PV.
// Online softmax: standard softmax is mathematically identical to the
// "cogview" variant (shift invariance).
// Row-group reduction: tid = ty*16+tx, so the 16 threads of a row form
// exactly one half-warp -> __shfl_xor_sync with width 16.
// ---------------------------------------------------------------------------
#define SM_PITCH 66
#define ATTN_SMEM (4 * 64 * SM_PITCH * (int)sizeof(float))  // 67584 B

__global__ __launch_bounds__(256) void attn_kernel(
    const float* __restrict__ mask,   // [B,1,1,S]
    const float* __restrict__ rel,    // [B,NH,S,S]
    float* __restrict__ out)          // [B,S,H]
{
    extern __shared__ float sm[];
    float* Qs = sm;                       // [64][SM_PITCH]
    float* Ks = sm + 64 * SM_PITCH;       // [64][SM_PITCH]
    float* Vs = sm + 2 * 64 * SM_PITCH;   // [64][SM_PITCH]
    float* Ps = sm + 3 * 64 * SM_PITCH;   // [64][SM_PITCH]

    const int qt = blockIdx.x;            // 0..15
    const int bh = blockIdx.y;            // 0..63
    const int b = bh >> 3;
    const int h = bh & 7;

    const float* qp = g_q + (size_t)bh * SEQ * HDIM;
    const float* kp = g_k + (size_t)bh * SEQ * HDIM;
    const float* vp = g_v + (size_t)bh * SEQ * HDIM;
    const float* relp = rel + (size_t)bh * SEQ * SEQ + (size_t)qt * 64 * SEQ;
    const float* mp = mask + (size_t)b * SEQ;

    const int tid = threadIdx.x;
    const int tx = tid & 15;
    const int ty = tid >> 4;

    // Load Q tile (64x64)
#pragma unroll
    for (int t = tid; t < 64 * 16; t += 256) {
        int r = t >> 4, c4 = (t & 15) * 4;
        float4 v4 = *(const float4*)&qp[(size_t)(qt * 64 + r) * HDIM + c4];
        Qs[r * SM_PITCH + c4 + 0] = v4.x; Qs[r * SM_PITCH + c4 + 1] = v4.y;
        Qs[r * SM_PITCH + c4 + 2] = v4.z; Qs[r * SM_PITCH + c4 + 3] = v4.w;
    }

    float m_run[4], l_run[4];
    float O[4][4];
#pragma unroll
    for (int i = 0; i < 4; i++) {
        m_run[i] = -1e30f;
        l_run[i] = 0.f;
#pragma unroll
        for (int j = 0; j < 4; j++) O[i][j] = 0.f;
    }

    const float scale = 0.125f;  // 1/sqrt(64)

    for (int kt = 0; kt < 16; kt++) {
        __syncthreads();  // prior iteration's PV reads (and Q load) complete
        // Load K and V tiles (64x64 each)
#pragma unroll
        for (int t = tid; t < 64 * 16; t += 256) {
            int r = t >> 4, c4 = (t & 15) * 4;
            float4 kv = *(const float4*)&kp[(size_t)(kt * 64 + r) * HDIM + c4];
            Ks[r * SM_PITCH + c4 + 0] = kv.x; Ks[r * SM_PITCH + c4 + 1] = kv.y;
            Ks[r * SM_PITCH + c4 + 2] = kv.z; Ks[r * SM_PITCH + c4 + 3] = kv.w;
            float4 vv = *(const float4*)&vp[(size_t)(kt * 64 + r) * HDIM + c4];
            Vs[r * SM_PITCH + c4 + 0] = vv.x; Vs[r * SM_PITCH + c4 + 1] = vv.y;
            Vs[r * SM_PITCH + c4 + 2] = vv.z; Vs[r * SM_PITCH + c4 + 3] = vv.w;
        }
        __syncthreads();

        // S tile = Q K^T (4x4 per thread)
        float S[4][4];
#pragma unroll
        for (int i = 0; i < 4; i++)
#pragma unroll
            for (int j = 0; j < 4; j++) S[i][j] = 0.f;

#pragma unroll 8
        for (int d = 0; d < HDIM; d++) {
            float q[4], k[4];
#pragma unroll
            for (int i = 0; i < 4; i++) q[i] = Qs[(ty + 16 * i) * SM_PITCH + d];
#pragma unroll
            for (int j = 0; j < 4; j++) k[j] = Ks[(tx + 16 * j) * SM_PITCH + d];
#pragma unroll
            for (int i = 0; i < 4; i++)
#pragma unroll
                for (int j = 0; j < 4; j++) S[i][j] = fmaf(q[i], k[j], S[i][j]);
        }

        // scale + rel bias + mask
#pragma unroll
        for (int i = 0; i < 4; i++) {
            int r = ty + 16 * i;
            const float* rrow = relp + (size_t)r * SEQ + kt * 64;
#pragma unroll
            for (int j = 0; j < 4; j++) {
                int c = tx + 16 * j;
                S[i][j] = fmaf(S[i][j], scale, rrow[c] + mp[kt * 64 + c]);
            }
        }

        // Online softmax per row (16 lanes per row = one half-warp)
#pragma unroll
        for (int i = 0; i < 4; i++) {
            float mt = fmaxf(fmaxf(S[i][0], S[i][1]), fmaxf(S[i][2], S[i][3]));
#pragma unroll
            for (int off = 8; off >= 1; off >>= 1)
                mt = fmaxf(mt, __shfl_xor_sync(0xffffffffu, mt, off, 16));
            float mnew = fmaxf(m_run[i], mt);
            float corr = __expf(m_run[i] - mnew);
            float psum = 0.f;
            int r = ty + 16 * i;
#pragma unroll
            for (int j = 0; j < 4; j++) {
                float p = __expf(S[i][j] - mnew);
                Ps[r * SM_PITCH + tx + 16 * j] = p;
                psum += p;
            }
#pragma unroll
            for (int off = 8; off >= 1; off >>= 1)
                psum += __shfl_xor_sync(0xffffffffu, psum, off, 16);
            l_run[i] = l_run[i] * corr + psum;
            m_run[i] = mnew;
#pragma unroll
            for (int j = 0; j < 4; j++) O[i][j] *= corr;
        }
        __syncthreads();

        // O += P @ V  (4x4 per thread; O cols = head dim)
#pragma unroll 8
        for (int c = 0; c < 64; c++) {
            float p[4], v[4];
#pragma unroll
            for (int i = 0; i < 4; i++) p[i] = Ps[(ty + 16 * i) * SM_PITCH + c];
#pragma unroll
            for (int j = 0; j < 4; j++) v[j] = Vs[c * SM_PITCH + tx + 16 * j];
#pragma unroll
            for (int i = 0; i < 4; i++)
#pragma unroll
                for (int j = 0; j < 4; j++) O[i][j] = fmaf(p[i], v[j], O[i][j]);
        }
    }

    // Write output [B, S, H]: row = qt*64 + r, col = h*64 + d
#pragma unroll
    for (int i = 0; i < 4; i++) {
        int r = ty + 16 * i;
        float inv_l = 1.f / l_run[i];
        size_t base = ((size_t)b * SEQ + qt * 64 + r) * HID + h * HDIM;
#pragma unroll
        for (int j = 0; j < 4; j++) {
            out[base + tx + 16 * j] = O[i][j] * inv_l;
        }
    }
}

// ---------------------------------------------------------------------------
extern "C" void kernel_launch(void* const* d_in, const int* in_sizes, int n_in,
                              void* d_out, int out_size)
{
    const float* hs   = (const float*)d_in[0];
    const float* mask = (const float*)d_in[1];
    const float* rel  = (const float*)d_in[2];
    const float* Wq   = (const float*)d_in[3];
    const float* bq   = (const float*)d_in[4];
    const float* Wk   = (const float*)d_in[5];
    const float* bk   = (const float*)d_in[6];
    const float* Wv   = (const float*)d_in[7];
    const float* bv   = (const float*)d_in[8];
    float* out = (float*)d_out;

    cudaFuncSetAttribute(attn_kernel,
                         cudaFuncAttributeMaxDynamicSharedMemorySize, ATTN_SMEM);

    dim3 g1(ROWS / QKV_BM, 24);           // 128 x 24
    qkv_kernel<<<g1, 256>>>(hs, Wq, bq, Wk, bk, Wv, bv);

    dim3 g2(SEQ / 64, BH);                // 16 x 64
    attn_kernel<<<g2, 256, ATTN_SMEM>>>(mask, rel, out);
}

// round 4
// speedup vs baseline: 2.0326x; 2.0326x over previous
#include <cuda_runtime.h>
#include <cuda_bf16.h>
#include <cuda_fp16.h>
#include <cstdint>

// Problem constants
#define Bsz 8
#define SEQ 1024
#define HID 512
#define NHEAD 8
#define HDIM 64
#define BH (Bsz*NHEAD)          // 64
#define ROWS (Bsz*SEQ)          // 8192

// Scratch for Q/K/V in [B, NH, S, HD] layout
__device__ float g_q[BH * SEQ * HDIM];
__device__ float g_k[BH * SEQ * HDIM];
__device__ float g_v[BH * SEQ * HDIM];

// ---------------------------------------------------------------------------
// m16n8k16 fp16 MMA with fp32 accumulate.
// A row-major 16x16:  a0=(g,2t..2t+1) a1=(g+8,2t..) a2=(g,2t+8..) a3=(g+8,2t+8..)
// B col-major 16x8:   b0=(k=2t..2t+1, n=g) b1=(k=2t+8.., n=g)
// C: c0=(g,2t) c1=(g,2t+1) c2=(g+8,2t) c3=(g+8,2t+1)
// ---------------------------------------------------------------------------
__device__ __forceinline__ void mma16816(float c[4],
    uint32_t a0, uint32_t a1, uint32_t a2, uint32_t a3,
    uint32_t b0, uint32_t b1)
{
    asm volatile(
        "mma.sync.aligned.m16n8k16.row.col.f32.f16.f16.f32 "
        "{%0,%1,%2,%3}, {%4,%5,%6,%7}, {%8,%9}, {%0,%1,%2,%3};\n"
        : "+f"(c[0]), "+f"(c[1]), "+f"(c[2]), "+f"(c[3])
        : "r"(a0), "r"(a1), "r"(a2), "r"(a3), "r"(b0), "r"(b1));
}

__device__ __forceinline__ uint32_t pack_half2(__half a, __half b) {
    return (uint32_t)__half_as_ushort(a) | ((uint32_t)__half_as_ushort(b) << 16);
}

// Split two floats into (hi, lo) half2 pairs: x = hi + lo to ~22 mantissa bits.
__device__ __forceinline__ void split2(float x, float y, uint32_t& hi, uint32_t& lo) {
    __half hx = __float2half_rn(x), hy = __float2half_rn(y);
    __half lx = __float2half_rn(x - __half2float(hx));
    __half ly = __float2half_rn(y - __half2float(hy));
    hi = pack_half2(hx, hy);
    lo = pack_half2(lx, ly);
}

// smem pitch (in 32-bit half2 units) for 32 half2 per row + 4 pad.
// bank of [row*PP + idx] with row = 8nt+g, idx = kc*8+t  ->  (4g+8kc+t)%32:
// conflict-free across the warp for every (nt, kc).
#define PP 36

// ---------------------------------------------------------------------------
// Fused QKV projection on fp16 split tensor cores.
// C[i,j] = sum_k X[i,k]*W[j,k] + b[j].  jb selects Q/K/V weight + head.
// Block: 128 threads (4 warps), tile 64 rows x 64 cols, BK=64.
// ---------------------------------------------------------------------------
__global__ __launch_bounds__(128) void qkv_kernel(
    const float* __restrict__ X,
    const float* __restrict__ Wq, const float* __restrict__ bq,
    const float* __restrict__ Wk, const float* __restrict__ bk,
    const float* __restrict__ Wv, const float* __restrict__ bv)
{
    __shared__ uint32_t Xhi[64 * PP], Xlo[64 * PP];
    __shared__ uint32_t Whi[64 * PP], Wlo[64 * PP];

    const int ib = blockIdx.x;          // 128 row tiles
    const int jb = blockIdx.y;          // 24 col tiles
    const int jsel = jb >> 3;           // 0=Q 1=K 2=V
    const int h = jb & 7;

    const float* W = (jsel == 0) ? Wq : (jsel == 1) ? Wk : Wv;
    const float* bias = (jsel == 0) ? bq : (jsel == 1) ? bk : bv;
    float* outp = (jsel == 0) ? g_q : (jsel == 1) ? g_k : g_v;

    const int tid = threadIdx.x;
    const int lane = tid & 31;
    const int w = tid >> 5;
    const int g = lane >> 2;
    const int tig = lane & 3;
    const int row0 = ib * 64;
    const int col0 = h * 64;

    float acc[8][4];
#pragma unroll
    for (int nt = 0; nt < 8; nt++)
#pragma unroll
        for (int j = 0; j < 4; j++) acc[nt][j] = 0.f;

    for (int kb = 0; kb < HID; kb += 64) {
        // Load + split X and W tiles (64x64 floats each)
#pragma unroll
        for (int u = 0; u < 8; u++) {
            int e = u * 128 + tid;
            int r = e >> 4, c4 = (e & 15) * 4;
            int o_ = r * PP + (c4 >> 1);
            float4 x4 = *(const float4*)&X[(size_t)(row0 + r) * HID + kb + c4];
            uint32_t h0, l0, h1, l1;
            split2(x4.x, x4.y, h0, l0);
            split2(x4.z, x4.w, h1, l1);
            Xhi[o_] = h0; Xhi[o_ + 1] = h1;
            Xlo[o_] = l0; Xlo[o_ + 1] = l1;
            float4 w4 = *(const float4*)&W[(size_t)(col0 + r) * HID + kb + c4];
            split2(w4.x, w4.y, h0, l0);
            split2(w4.z, w4.w, h1, l1);
            Whi[o_] = h0; Whi[o_ + 1] = h1;
            Wlo[o_] = l0; Wlo[o_ + 1] = l1;
        }
        __syncthreads();

#pragma unroll
        for (int kc = 0; kc < 4; kc++) {
            int ra = (w * 16 + g) * PP + kc * 8 + tig;
            uint32_t ah0 = Xhi[ra],     ah1 = Xhi[ra + 8 * PP];
            uint32_t ah2 = Xhi[ra + 4], ah3 = Xhi[ra + 8 * PP + 4];
            uint32_t al0 = Xlo[ra],     al1 = Xlo[ra + 8 * PP];
            uint32_t al2 = Xlo[ra + 4], al3 = Xlo[ra + 8 * PP + 4];
#pragma unroll
            for (int nt = 0; nt < 8; nt++) {
                int rb = (nt * 8 + g) * PP + kc * 8 + tig;
                uint32_t bh0 = Whi[rb], bh1 = Whi[rb + 4];
                uint32_t bl0 = Wlo[rb], bl1 = Wlo[rb + 4];
                mma16816(acc[nt], ah0, ah1, ah2, ah3, bh0, bh1);
                mma16816(acc[nt], ah0, ah1, ah2, ah3, bl0, bl1);
                mma16816(acc[nt], al0, al1, al2, al3, bh0, bh1);
            }
        }
        __syncthreads();
    }

    // Epilogue: add bias, write in [B, NH, S, HD] layout
    const int grow0 = row0 + w * 16 + g;
    const int grow1 = grow0 + 8;
    const int b0i = grow0 >> 10, s0 = grow0 & 1023;
    const int b1i = grow1 >> 10, s1 = grow1 & 1023;
    size_t base0 = ((size_t)(b0i * NHEAD + h) * SEQ + s0) * HDIM;
    size_t base1 = ((size_t)(b1i * NHEAD + h) * SEQ + s1) * HDIM;
#pragma unroll
    for (int nt = 0; nt < 8; nt++) {
        int d = nt * 8 + 2 * tig;
        float bv0 = bias[col0 + d], bv1 = bias[col0 + d + 1];
        *(float2*)&outp[base0 + d] = make_float2(acc[nt][0] + bv0, acc[nt][1] + bv1);
        *(float2*)&outp[base1 + d] = make_float2(acc[nt][2] + bv0, acc[nt][3] + bv1);
    }
}

// ---------------------------------------------------------------------------
// Flash attention on fp16 split tensor cores.
// Block = (q-tile of 64 rows, b*NH+h), 128 threads = 4 warps.
// Warp w owns q rows w*16..w*16+15; Q A-fragments (pre-scaled by 1/8) in regs.
// P: QK C-fragment layout == m16n8k16 A-fragment layout -> pure packs, no shfl.
// V transposed at smem-store time into [hd][key-pair half2] layout.
// ---------------------------------------------------------------------------
__global__ __launch_bounds__(128) void attn_kernel(
    const float* __restrict__ mask,   // [B,1,1,S]
    const float* __restrict__ rel,    // [B,NH,S,S]
    float* __restrict__ out)          // [B,S,H]
{
    __shared__ uint32_t Khi[64 * PP], Klo[64 * PP];
    __shared__ uint32_t Vhi[64 * PP], Vlo[64 * PP];
    __shared__ float Ms[64];

    const int qt = blockIdx.x;        // 0..15
    const int bh = blockIdx.y;        // 0..63
    const int b = bh >> 3;
    const int h = bh & 7;

    const float* qp = g_q + (size_t)bh * SEQ * HDIM;
    const float* kp = g_k + (size_t)bh * SEQ * HDIM;
    const float* vp = g_v + (size_t)bh * SEQ * HDIM;
    const float* relp = rel + (size_t)bh * SEQ * SEQ;
    const float* mp = mask + (size_t)b * SEQ;

    const int tid = threadIdx.x;
    const int lane = tid & 31;
    const int w = tid >> 5;
    const int g = lane >> 2;
    const int tig = lane & 3;
    const unsigned FULL = 0xffffffffu;

    // Stage Q (pre-scaled by 1/8, exact) through Khi/Klo, pull A-frags to regs
#pragma unroll
    for (int u = 0; u < 8; u++) {
        int e = u * 128 + tid;
        int r = e >> 4, c4 = (e & 15) * 4;
        int o_ = r * PP + (c4 >> 1);
        float4 q4 = *(const float4*)&qp[(size_t)(qt * 64 + r) * HDIM + c4];
        uint32_t h0, l0, h1, l1;
        split2(q4.x * 0.125f, q4.y * 0.125f, h0, l0);
        split2(q4.z * 0.125f, q4.w * 0.125f, h1, l1);
        Khi[o_] = h0; Khi[o_ + 1] = h1;
        Klo[o_] = l0; Klo[o_ + 1] = l1;
    }
    __syncthreads();

    uint32_t qh[4][4], ql[4][4];
#pragma unroll
    for (int kc = 0; kc < 4; kc++) {
        int ra = (w * 16 + g) * PP + kc * 8 + tig;
        qh[kc][0] = Khi[ra];     qh[kc][1] = Khi[ra + 8 * PP];
        qh[kc][2] = Khi[ra + 4]; qh[kc][3] = Khi[ra + 8 * PP + 4];
        ql[kc][0] = Klo[ra];     ql[kc][1] = Klo[ra + 8 * PP];
        ql[kc][2] = Klo[ra + 4]; ql[kc][3] = Klo[ra + 8 * PP + 4];
    }
    __syncthreads();

    float o[8][4];
#pragma unroll
    for (int nt = 0; nt < 8; nt++)
#pragma unroll
        for (int j = 0; j < 4; j++) o[nt][j] = 0.f;
    float m0 = -1e30f, m1 = -1e30f, l0r = 0.f, l1r = 0.f;

    const int rA = qt * 64 + w * 16 + g;   // q row (first half)

    for (int kt = 0; kt < 16; kt++) {
        // K tile: rows=key (n-major), half2 over hd (k) -- natural orientation
#pragma unroll
        for (int u = 0; u < 8; u++) {
            int e = u * 128 + tid;
            int r = e >> 4, c4 = (e & 15) * 4;
            int o_ = r * PP + (c4 >> 1);
            float4 k4 = *(const float4*)&kp[(size_t)(kt * 64 + r) * HDIM + c4];
            uint32_t h0, l0, h1, l1;
            split2(k4.x, k4.y, h0, l0);
            split2(k4.z, k4.w, h1, l1);
            Khi[o_] = h0; Khi[o_ + 1] = h1;
            Klo[o_] = l0; Klo[o_ + 1] = l1;
        }
        // V tile transposed: rows=hd (n-major), half2 over key pairs (k)
#pragma unroll
        for (int i = 0; i < 8; i++) {
            int kpi = w * 8 + i;                      // key pair 0..31
            const float* vb = vp + (size_t)(kt * 64 + 2 * kpi) * HDIM;
#pragma unroll
            for (int dh = 0; dh < 2; dh++) {
                int d = lane + 32 * dh;
                float v0 = vb[d];
                float v1 = vb[HDIM + d];
                uint32_t hh, ll;
                split2(v0, v1, hh, ll);
                Vhi[d * PP + kpi] = hh;
                Vlo[d * PP + kpi] = ll;
            }
        }
        if (tid < 64) Ms[tid] = mp[kt * 64 + tid];
        __syncthreads();

        // S = Q K^T (scale pre-folded into Q)
        float s[8][4];
#pragma unroll
        for (int nt = 0; nt < 8; nt++)
#pragma unroll
            for (int j = 0; j < 4; j++) s[nt][j] = 0.f;

#pragma unroll
        for (int kc = 0; kc < 4; kc++) {
#pragma unroll
            for (int nt = 0; nt < 8; nt++) {
                int rb = (nt * 8 + g) * PP + kc * 8 + tig;
                uint32_t bh0 = Khi[rb], bh1 = Khi[rb + 4];
                uint32_t bl0 = Klo[rb], bl1 = Klo[rb + 4];
                mma16816(s[nt], qh[kc][0], qh[kc][1], qh[kc][2], qh[kc][3], bh0, bh1);
                mma16816(s[nt], qh[kc][0], qh[kc][1], qh[kc][2], qh[kc][3], bl0, bl1);
                mma16816(s[nt], ql[kc][0], ql[kc][1], ql[kc][2], ql[kc][3], bh0, bh1);
            }
        }

        // + rel bias + mask
        const float* rrA = relp + (size_t)rA * SEQ + kt * 64;
        const float* rrB = rrA + (size_t)8 * SEQ;
#pragma unroll
        for (int nt = 0; nt < 8; nt++) {
            int c = nt * 8 + 2 * tig;
            float2 bA = *(const float2*)&rrA[c];
            float2 bB = *(const float2*)&rrB[c];
            float mm0 = Ms[c], mm1 = Ms[c + 1];
            s[nt][0] += bA.x + mm0;
            s[nt][1] += bA.y + mm1;
            s[nt][2] += bB.x + mm0;
            s[nt][3] += bB.y + mm1;
        }

        // Online softmax (row halves live in quads; shfl width 4)
        float mx0 = -1e30f, mx1 = -1e30f;
#pragma unroll
        for (int nt = 0; nt < 8; nt++) {
            mx0 = fmaxf(mx0, fmaxf(s[nt][0], s[nt][1]));
            mx1 = fmaxf(mx1, fmaxf(s[nt][2], s[nt][3]));
        }
        mx0 = fmaxf(mx0, __shfl_xor_sync(FULL, mx0, 1, 4));
        mx0 = fmaxf(mx0, __shfl_xor_sync(FULL, mx0, 2, 4));
        mx1 = fmaxf(mx1, __shfl_xor_sync(FULL, mx1, 1, 4));
        mx1 = fmaxf(mx1, __shfl_xor_sync(FULL, mx1, 2, 4));
        float mn0 = fmaxf(m0, mx0), mn1 = fmaxf(m1, mx1);
        float cor0 = __expf(m0 - mn0), cor1 = __expf(m1 - mn1);

        float sum0 = 0.f, sum1 = 0.f;
#pragma unroll
        for (int nt = 0; nt < 8; nt++) {
            s[nt][0] = __expf(s[nt][0] - mn0); sum0 += s[nt][0];
            s[nt][1] = __expf(s[nt][1] - mn0); sum0 += s[nt][1];
            s[nt][2] = __expf(s[nt][2] - mn1); sum1 += s[nt][2];
            s[nt][3] = __expf(s[nt][3] - mn1); sum1 += s[nt][3];
        }
        sum0 += __shfl_xor_sync(FULL, sum0, 1, 4);
        sum0 += __shfl_xor_sync(FULL, sum0, 2, 4);
        sum1 += __shfl_xor_sync(FULL, sum1, 1, 4);
        sum1 += __shfl_xor_sync(FULL, sum1, 2, 4);
        l0r = l0r * cor0 + sum0;  m0 = mn0;
        l1r = l1r * cor1 + sum1;  m1 = mn1;

#pragma unroll
        for (int nt = 0; nt < 8; nt++) {
            o[nt][0] *= cor0; o[nt][1] *= cor0;
            o[nt][2] *= cor1; o[nt][3] *= cor1;
        }

        // O += P @ V.  P C-frag == A-frag layout: pure packs, no shuffles.
#pragma unroll
        for (int kk = 0; kk < 4; kk++) {
            uint32_t ah[4], al[4];
            split2(s[2 * kk][0],     s[2 * kk][1],     ah[0], al[0]);
            split2(s[2 * kk][2],     s[2 * kk][3],     ah[1], al[1]);
            split2(s[2 * kk + 1][0], s[2 * kk + 1][1], ah[2], al[2]);
            split2(s[2 * kk + 1][2], s[2 * kk + 1][3], ah[3], al[3]);
#pragma unroll
            for (int nt2 = 0; nt2 < 8; nt2++) {
                int rb = (nt2 * 8 + g) * PP + kk * 8 + tig;
                uint32_t bh0 = Vhi[rb], bh1 = Vhi[rb + 4];
                uint32_t bl0 = Vlo[rb], bl1 = Vlo[rb + 4];
                mma16816(o[nt2], ah[0], ah[1], ah[2], ah[3], bh0, bh1);
                mma16816(o[nt2], ah[0], ah[1], ah[2], ah[3], bl0, bl1);
                mma16816(o[nt2], al[0], al[1], al[2], al[3], bh0, bh1);
            }
        }
        __syncthreads();
    }

    // Epilogue: normalize, write [B, S, H]
    float il0 = 1.f / l0r, il1 = 1.f / l1r;
    size_t base0 = ((size_t)b * SEQ + rA) * HID + h * HDIM;
    size_t base1 = base0 + (size_t)8 * HID;
#pragma unroll
    for (int nt = 0; nt < 8; nt++) {
        int d = nt * 8 + 2 * tig;
        *(float2*)&out[base0 + d] = make_float2(o[nt][0] * il0, o[nt][1] * il0);
        *(float2*)&out[base1 + d] = make_float2(o[nt][2] * il1, o[nt][3] * il1);
    }
}

// ---------------------------------------------------------------------------
extern "C" void kernel_launch(void* const* d_in, const int* in_sizes, int n_in,
                              void* d_out, int out_size)
{
    const float* hs   = (const float*)d_in[0];
    const float* mask = (const float*)d_in[1];
    const float* rel  = (const float*)d_in[2];
    const float* Wq   = (const float*)d_in[3];
    const float* bq   = (const float*)d_in[4];
    const float* Wk   = (const float*)d_in[5];
    const float* bk   = (const float*)d_in[6];
    const float* Wv   = (const float*)d_in[7];
    const float* bv   = (const float*)d_in[8];
    float* out = (float*)d_out;

    dim3 g1(ROWS / 64, 24);
    qkv_kernel<<<g1, 128>>>(hs, Wq, bq, Wk, bk, Wv, bv);

    dim3 g2(SEQ / 64, BH);
    attn_kernel<<<g2, 128>>>(mask, rel, out);
}

// round 11
// speedup vs baseline: 2.5954x; 1.2769x over previous
#include <cuda_runtime.h>
#include <cuda_bf16.h>
#include <cuda_fp16.h>
#include <cstdint>

// Problem constants
#define Bsz 8
#define SEQ 1024
#define HID 512
#define NHEAD 8
#define HDIM 64
#define BH (Bsz*NHEAD)          // 64
#define ROWS (Bsz*SEQ)          // 8192
#define XROWS (ROWS + 3*HID)    // 9728 : X rows then Wq,Wk,Wv rows

// ---------------------------------------------------------------------------
// Global scratch (pre-split operands, all half2-packed in uint32)
// ---------------------------------------------------------------------------
__device__ uint32_t g_xh[XROWS * (HID/2)];      // X/W hi  [row][256]
__device__ uint32_t g_xl[XROWS * (HID/2)];      // X/W lo
__device__ uint32_t g_qh[BH * SEQ * (HDIM/2)];  // Q hi    [bh][s][32]
__device__ uint32_t g_ql[BH * SEQ * (HDIM/2)];
__device__ uint32_t g_kh[BH * SEQ * (HDIM/2)];  // K hi (pre-scaled by 1/8)
__device__ uint32_t g_kl[BH * SEQ * (HDIM/2)];
__device__ float    g_v [BH * SEQ * HDIM];      // V fp32 [bh][s][d]
__device__ uint32_t g_vth[BH * HDIM * (SEQ/2)]; // V^T hi [bh][d][s-pair]
__device__ uint32_t g_vtl[BH * HDIM * (SEQ/2)];

// ---------------------------------------------------------------------------
// MMA + helpers
// ---------------------------------------------------------------------------
__device__ __forceinline__ void mma16816(float c[4],
    uint32_t a0, uint32_t a1, uint32_t a2, uint32_t a3,
    uint32_t b0, uint32_t b1)
{
    asm volatile(
        "mma.sync.aligned.m16n8k16.row.col.f32.f16.f16.f32 "
        "{%0,%1,%2,%3}, {%4,%5,%6,%7}, {%8,%9}, {%0,%1,%2,%3};\n"
        : "+f"(c[0]), "+f"(c[1]), "+f"(c[2]), "+f"(c[3])
        : "r"(a0), "r"(a1), "r"(a2), "r"(a3), "r"(b0), "r"(b1));
}

__device__ __forceinline__ uint32_t pack_half2(__half a, __half b) {
    return (uint32_t)__half_as_ushort(a) | ((uint32_t)__half_as_ushort(b) << 16);
}
__device__ __forceinline__ void split2(float x, float y, uint32_t& hi, uint32_t& lo) {
    __half hx = __float2half_rn(x), hy = __float2half_rn(y);
    __half lx = __float2half_rn(x - __half2float(hx));
    __half ly = __float2half_rn(y - __half2float(hy));
    hi = pack_half2(hx, hy);
    lo = pack_half2(ly, ly);  // placeholder overwritten below
    lo = pack_half2(lx, ly);
}

__device__ __forceinline__ void cp16(uint32_t dst_smem, const void* src) {
    asm volatile("cp.async.cg.shared.global [%0], [%1], 16;\n"
                 :: "r"(dst_smem), "l"(src));
}
#define CP_COMMIT() asm volatile("cp.async.commit_group;\n")
#define CP_WAIT(N)  asm volatile("cp.async.wait_group %0;\n" :: "n"(N))

// smem pitch in uint32 (32 data + 4 pad): frag bank = (4g+8kc+t)%32, clean.
#define PP 36
#define TSTRIDE (64 * PP)       // 2304 u32 per tile

// ---------------------------------------------------------------------------
// 1) Split X (8192 rows) and W (1536 rows: Wq,Wk,Wv) into hi/lo half2.
//    One block per row, 128 threads, 1 float4 each.
// ---------------------------------------------------------------------------
__global__ __launch_bounds__(128) void split_kernel(
    const float* __restrict__ X,
    const float* __restrict__ Wq, const float* __restrict__ Wk,
    const float* __restrict__ Wv)
{
    const int r = blockIdx.x;
    const int tid = threadIdx.x;
    const float* src;
    if (r < ROWS) src = X + (size_t)r * HID;
    else {
        int wr = r - ROWS;
        const float* W = (wr >> 9) == 0 ? Wq : (wr >> 9) == 1 ? Wk : Wv;
        src = W + (size_t)(wr & 511) * HID;
    }
    float4 v4 = *(const float4*)&src[tid * 4];
    uint32_t h0, l0, h1, l1;
    split2(v4.x, v4.y, h0, l0);
    split2(v4.z, v4.w, h1, l1);
    size_t o = (size_t)r * (HID/2) + tid * 2;
    g_xh[o] = h0; g_xh[o + 1] = h1;
    g_xl[o] = l0; g_xl[o + 1] = l1;
}

// ---------------------------------------------------------------------------
// 2) QKV GEMM on pre-split operands. cp.async 2-stage pipeline.
//    Tile 64x64, BK=64 (32 u32), 128 threads / 4 warps.
//    Writes Q/K pre-split (K scaled by 1/8), V in fp32.
// ---------------------------------------------------------------------------
__device__ __forceinline__ void qkv_issue(
    uint32_t* smu, int st, int sg, int tid, int row0, int wrow0)
{
    const int kb32 = st * 32;           // u32 col offset within 256-wide row
    const uint32_t base = sg * (4 * TSTRIDE);
#pragma unroll
    for (int u = 0; u < 16; u++) {
        int t = u * 128 + tid;
        int arr = t >> 9;
        int rem = t & 511;
        int r = rem >> 3, seg = rem & 7;
        const uint32_t* src;
        if (arr == 0)      src = g_xh + (size_t)(row0 + r) * 256 + kb32 + seg * 4;
        else if (arr == 1) src = g_xl + (size_t)(row0 + r) * 256 + kb32 + seg * 4;
        else if (arr == 2) src = g_xh + (size_t)(wrow0 + r) * 256 + kb32 + seg * 4;
        else               src = g_xl + (size_t)(wrow0 + r) * 256 + kb32 + seg * 4;
        uint32_t dst = (uint32_t)__cvta_generic_to_shared(
            &smu[base + arr * TSTRIDE + r * PP + seg * 4]);
        cp16(dst, src);
    }
    CP_COMMIT();
}

__global__ __launch_bounds__(128, 2) void qkv_kernel(
    const float* __restrict__ bq, const float* __restrict__ bk,
    const float* __restrict__ bv)
{
    extern __shared__ uint32_t smu[];   // 2 stages x 4 tiles x 2304 = 73728 B
    const int ib = blockIdx.x;          // 128 row tiles
    const int jb = blockIdx.y;          // 24 col tiles
    const int jsel = jb >> 3;           // 0=Q 1=K 2=V
    const int h = jb & 7;

    const float* bias = (jsel == 0) ? bq : (jsel == 1) ? bk : bv;

    const int tid = threadIdx.x;
    const int lane = tid & 31;
    const int w = tid >> 5;
    const int g = lane >> 2;
    const int tig = lane & 3;
    const int row0 = ib * 64;
    const int wrow0 = ROWS + jsel * HID + h * 64;

    float acc[8][4];
#pragma unroll
    for (int nt = 0; nt < 8; nt++)
#pragma unroll
        for (int j = 0; j < 4; j++) acc[nt][j] = 0.f;

    qkv_issue(smu, 0, 0, tid, row0, wrow0);

    for (int st = 0; st < 8; st++) {
        int p = st & 1;
        if (st < 7) { qkv_issue(smu, st + 1, 1 - p, tid, row0, wrow0); CP_WAIT(1); }
        else CP_WAIT(0);
        __syncthreads();

        const uint32_t* Xhi = smu + p * (4 * TSTRIDE);
        const uint32_t* Xlo = Xhi + TSTRIDE;
        const uint32_t* Whi = Xhi + 2 * TSTRIDE;
        const uint32_t* Wlo = Xhi + 3 * TSTRIDE;

#pragma unroll
        for (int kc = 0; kc < 4; kc++) {
            int ra = (w * 16 + g) * PP + kc * 8 + tig;
            uint32_t ah0 = Xhi[ra],     ah1 = Xhi[ra + 8 * PP];
            uint32_t ah2 = Xhi[ra + 4], ah3 = Xhi[ra + 8 * PP + 4];
            uint32_t al0 = Xlo[ra],     al1 = Xlo[ra + 8 * PP];
            uint32_t al2 = Xlo[ra + 4], al3 = Xlo[ra + 8 * PP + 4];
#pragma unroll
            for (int nt = 0; nt < 8; nt++) {
                int rb = (nt * 8 + g) * PP + kc * 8 + tig;
                uint32_t bh0 = Whi[rb], bh1 = Whi[rb + 4];
                uint32_t bl0 = Wlo[rb], bl1 = Wlo[rb + 4];
                mma16816(acc[nt], ah0, ah1, ah2, ah3, bh0, bh1);
                mma16816(acc[nt], ah0, ah1, ah2, ah3, bl0, bl1);
                mma16816(acc[nt], al0, al1, al2, al3, bh0, bh1);
            }
        }
        __syncthreads();
    }

    // Epilogue
    const int grow0 = row0 + w * 16 + g;
    const int grow1 = grow0 + 8;
    const int b0i = grow0 >> 10, s0 = grow0 & 1023;
    const int b1i = grow1 >> 10, s1 = grow1 & 1023;
    const int bh0 = b0i * NHEAD + h, bh1 = b1i * NHEAD + h;

    if (jsel == 2) {
        // V in fp32 [bh][s][d]
        size_t base0 = ((size_t)bh0 * SEQ + s0) * HDIM;
        size_t base1 = ((size_t)bh1 * SEQ + s1) * HDIM;
#pragma unroll
        for (int nt = 0; nt < 8; nt++) {
            int d = nt * 8 + 2 * tig;
            float bv0 = bias[h * 64 + d], bv1 = bias[h * 64 + d + 1];
            *(float2*)&g_v[base0 + d] = make_float2(acc[nt][0] + bv0, acc[nt][1] + bv1);
            *(float2*)&g_v[base1 + d] = make_float2(acc[nt][2] + bv0, acc[nt][3] + bv1);
        }
    } else {
        uint32_t* oh = (jsel == 0) ? g_qh : g_kh;
        uint32_t* ol = (jsel == 0) ? g_ql : g_kl;
        float sc = (jsel == 0) ? 1.0f : 0.125f;   // fold 1/sqrt(64) into K (exact)
        size_t base0 = ((size_t)bh0 * SEQ + s0) * 32;
        size_t base1 = ((size_t)bh1 * SEQ + s1) * 32;
#pragma unroll
        for (int nt = 0; nt < 8; nt++) {
            int d = nt * 8 + 2 * tig;
            int uc = nt * 4 + tig;
            float bv0 = bias[h * 64 + d], bv1 = bias[h * 64 + d + 1];
            uint32_t hi, lo;
            split2((acc[nt][0] + bv0) * sc, (acc[nt][1] + bv1) * sc, hi, lo);
            oh[base0 + uc] = hi; ol[base0 + uc] = lo;
            split2((acc[nt][2] + bv0) * sc, (acc[nt][3] + bv1) * sc, hi, lo);
            oh[base1 + uc] = hi; ol[base1 + uc] = lo;
        }
    }
}

// ---------------------------------------------------------------------------
// 3) Transpose + split V:  g_v [bh][s][d] -> g_vth/g_vtl [bh][d][s-pair]
//    Block: 256 threads, tile 64(s) x 64(d).
// ---------------------------------------------------------------------------
__global__ __launch_bounds__(256) void vtrans_kernel()
{
    __shared__ float Vs[64][65];
    const int stile = blockIdx.x;       // 0..15
    const int bh = blockIdx.y;          // 0..63
    const int tid = threadIdx.x;

#pragma unroll
    for (int u = 0; u < 4; u++) {
        int e = u * 256 + tid;
        int r = e >> 4, c4 = (e & 15) * 4;
        float4 v4 = *(const float4*)&g_v[((size_t)bh * SEQ + stile * 64 + r) * HDIM + c4];
        Vs[r][c4 + 0] = v4.x; Vs[r][c4 + 1] = v4.y;
        Vs[r][c4 + 2] = v4.z; Vs[r][c4 + 3] = v4.w;
    }
    __syncthreads();

    const int d = tid >> 2;
    const int q = tid & 3;
    size_t obase = ((size_t)bh * HDIM + d) * (SEQ/2) + stile * 32;
#pragma unroll
    for (int i = 0; i < 8; i++) {
        int sp = q * 8 + i;
        uint32_t hi, lo;
        split2(Vs[2 * sp][d], Vs[2 * sp + 1][d], hi, lo);
        g_vth[obase + sp] = hi;
        g_vtl[obase + sp] = lo;
    }
}

// ---------------------------------------------------------------------------
// 4) Flash attention: cp.async double-buffered, all operands pre-split.
//    Block = (64-row q-tile, bh), 128 threads / 4 warps.
//    Stage layout (u32): Khi@0 Klo@2304 Vh@4608 Vl@6912 Ms@9216(+64)
// ---------------------------------------------------------------------------
#define ASTG 9280

__device__ __forceinline__ void attn_issue(
    uint32_t* smu, int kt, int sg, int tid,
    const uint32_t* khp, const uint32_t* klp,
    const uint32_t* vhp, const uint32_t* vlp, const float* mp)
{
    const uint32_t base = sg * ASTG;
#pragma unroll
    for (int u = 0; u < 16; u++) {
        int t = u * 128 + tid;
        int arr = t >> 9;
        int rem = t & 511;
        int r = rem >> 3, seg = rem & 7;
        const uint32_t* src;
        if (arr == 0)      src = khp + (size_t)(kt * 64 + r) * 32 + seg * 4;
        else if (arr == 1) src = klp + (size_t)(kt * 64 + r) * 32 + seg * 4;
        else if (arr == 2) src = vhp + (size_t)r * (SEQ/2) + kt * 32 + seg * 4;
        else               src = vlp + (size_t)r * (SEQ/2) + kt * 32 + seg * 4;
        uint32_t dst = (uint32_t)__cvta_generic_to_shared(
            &smu[base + arr * TSTRIDE + r * PP + seg * 4]);
        cp16(dst, src);
    }
    if (tid < 16)
        cp16((uint32_t)__cvta_generic_to_shared(&smu[base + 9216 + tid * 4]),
             mp + kt * 64 + tid * 4);
    CP_COMMIT();
}

__global__ __launch_bounds__(128, 2) void attn_kernel(
    const float* __restrict__ mask,   // [B,1,1,S]
    const float* __restrict__ rel,    // [B,NH,S,S]
    float* __restrict__ out)          // [B,S,H]
{
    extern __shared__ uint32_t smu[];   // 2 * 9280 u32 = 74240 B

    const int qt = blockIdx.x;        // 0..15
    const int bh = blockIdx.y;        // 0..63
    const int b = bh >> 3;
    const int h = bh & 7;

    const uint32_t* qhp = g_qh + (size_t)bh * SEQ * 32;
    const uint32_t* qlp = g_ql + (size_t)bh * SEQ * 32;
    const uint32_t* khp = g_kh + (size_t)bh * SEQ * 32;
    const uint32_t* klp = g_kl + (size_t)bh * SEQ * 32;
    const uint32_t* vhp = g_vth + (size_t)bh * HDIM * (SEQ/2);
    const uint32_t* vlp = g_vtl + (size_t)bh * HDIM * (SEQ/2);
    const float* relp = rel + (size_t)bh * SEQ * SEQ;
    const float* mp = mask + (size_t)b * SEQ;

    const int tid = threadIdx.x;
    const int lane = tid & 31;
    const int w = tid >> 5;
    const int g = lane >> 2;
    const int tig = lane & 3;
    const unsigned FULL = 0xffffffffu;

    attn_issue(smu, 0, 0, tid, khp, klp, vhp, vlp, mp);  // prefetch tile 0

    // Q A-fragments straight from global (latency overlaps the prefetch)
    const int rA = qt * 64 + w * 16 + g;
    uint32_t qh[4][4], ql[4][4];
#pragma unroll
    for (int kc = 0; kc < 4; kc++) {
        size_t r0 = (size_t)rA * 32 + kc * 8 + tig;
        size_t r1 = (size_t)(rA + 8) * 32 + kc * 8 + tig;
        qh[kc][0] = qhp[r0]; qh[kc][1] = qhp[r1];
        qh[kc][2] = qhp[r0 + 4]; qh[kc][3] = qhp[r1 + 4];
        ql[kc][0] = qlp[r0]; ql[kc][1] = qlp[r1];
        ql[kc][2] = qlp[r0 + 4]; ql[kc][3] = qlp[r1 + 4];
    }

    float o[8][4];
#pragma unroll
    for (int nt = 0; nt < 8; nt++)
#pragma unroll
        for (int j = 0; j < 4; j++) o[nt][j] = 0.f;
    float m0 = -1e30f, m1 = -1e30f, l0r = 0.f, l1r = 0.f;

    for (int kt = 0; kt < 16; kt++) {
        int p = kt & 1;
        if (kt < 15) {
            attn_issue(smu, kt + 1, 1 - p, tid, khp, klp, vhp, vlp, mp);
            CP_WAIT(1);
        } else CP_WAIT(0);
        __syncthreads();

        const uint32_t* Khi = smu + p * ASTG;
        const uint32_t* Klo = Khi + TSTRIDE;
        const uint32_t* Vhi = Khi + 2 * TSTRIDE;
        const uint32_t* Vlo = Khi + 3 * TSTRIDE;
        const float* Msf = (const float*)(Khi + 9216);

        // Prefetch rel-bias into registers: DRAM latency overlaps S-MMA loop
        const float* rrA = relp + (size_t)rA * SEQ + kt * 64;
        const float* rrB = rrA + (size_t)8 * SEQ;
        float2 bA[8], bB[8];
#pragma unroll
        for (int nt = 0; nt < 8; nt++) {
            int c = nt * 8 + 2 * tig;
            bA[nt] = *(const float2*)&rrA[c];
            bB[nt] = *(const float2*)&rrB[c];
        }

        // S = Q K^T (scale folded into K)
        float s[8][4];
#pragma unroll
        for (int nt = 0; nt < 8; nt++)
#pragma unroll
            for (int j = 0; j < 4; j++) s[nt][j] = 0.f;

#pragma unroll
        for (int kc = 0; kc < 4; kc++) {
#pragma unroll
            for (int nt = 0; nt < 8; nt++) {
                int rb = (nt * 8 + g) * PP + kc * 8 + tig;
                uint32_t bh0 = Khi[rb], bh1 = Khi[rb + 4];
                uint32_t bl0 = Klo[rb], bl1 = Klo[rb + 4];
                mma16816(s[nt], qh[kc][0], qh[kc][1], qh[kc][2], qh[kc][3], bh0, bh1);
                mma16816(s[nt], qh[kc][0], qh[kc][1], qh[kc][2], qh[kc][3], bl0, bl1);
                mma16816(s[nt], ql[kc][0], ql[kc][1], ql[kc][2], ql[kc][3], bh0, bh1);
            }
        }

        // + rel bias + mask
#pragma unroll
        for (int nt = 0; nt < 8; nt++) {
            int c = nt * 8 + 2 * tig;
            float mm0 = Msf[c], mm1 = Msf[c + 1];
            s[nt][0] += bA[nt].x + mm0;
            s[nt][1] += bA[nt].y + mm1;
            s[nt][2] += bB[nt].x + mm0;
            s[nt][3] += bB[nt].y + mm1;
        }

        // Online softmax (row halves live in quads; shfl width 4)
        float mx0 = -1e30f, mx1 = -1e30f;
#pragma unroll
        for (int nt = 0; nt < 8; nt++) {
            mx0 = fmaxf(mx0, fmaxf(s[nt][0], s[nt][1]));
            mx1 = fmaxf(mx1, fmaxf(s[nt][2], s[nt][3]));
        }
        mx0 = fmaxf(mx0, __shfl_xor_sync(FULL, mx0, 1, 4));
        mx0 = fmaxf(mx0, __shfl_xor_sync(FULL, mx0, 2, 4));
        mx1 = fmaxf(mx1, __shfl_xor_sync(FULL, mx1, 1, 4));
        mx1 = fmaxf(mx1, __shfl_xor_sync(FULL, mx1, 2, 4));
        float mn0 = fmaxf(m0, mx0), mn1 = fmaxf(m1, mx1);
        float cor0 = __expf(m0 - mn0), cor1 = __expf(m1 - mn1);

        float sum0 = 0.f, sum1 = 0.f;
#pragma unroll
        for (int nt = 0; nt < 8; nt++) {
            s[nt][0] = __expf(s[nt][0] - mn0); sum0 += s[nt][0];
            s[nt][1] = __expf(s[nt][1] - mn0); sum0 += s[nt][1];
            s[nt][2] = __expf(s[nt][2] - mn1); sum1 += s[nt][2];
            s[nt][3] = __expf(s[nt][3] - mn1); sum1 += s[nt][3];
        }
        sum0 += __shfl_xor_sync(FULL, sum0, 1, 4);
        sum0 += __shfl_xor_sync(FULL, sum0, 2, 4);
        sum1 += __shfl_xor_sync(FULL, sum1, 1, 4);
        sum1 += __shfl_xor_sync(FULL, sum1, 2, 4);
        l0r = l0r * cor0 + sum0;  m0 = mn0;
        l1r = l1r * cor1 + sum1;  m1 = mn1;

#pragma unroll
        for (int nt = 0; nt < 8; nt++) {
            o[nt][0] *= cor0; o[nt][1] *= cor0;
            o[nt][2] *= cor1; o[nt][3] *= cor1;
        }

        // O += P @ V.  P C-frag == A-frag layout: pure packs, no shuffles.
#pragma unroll
        for (int kk = 0; kk < 4; kk++) {
            uint32_t ah[4], al[4];
            split2(s[2 * kk][0],     s[2 * kk][1],     ah[0], al[0]);
            split2(s[2 * kk][2],     s[2 * kk][3],     ah[1], al[1]);
            split2(s[2 * kk + 1][0], s[2 * kk + 1][1], ah[2], al[2]);
            split2(s[2 * kk + 1][2], s[2 * kk + 1][3], ah[3], al[3]);
#pragma unroll
            for (int nt2 = 0; nt2 < 8; nt2++) {
                int rb = (nt2 * 8 + g) * PP + kk * 8 + tig;
                uint32_t bh0 = Vhi[rb], bh1 = Vhi[rb + 4];
                uint32_t bl0 = Vlo[rb], bl1 = Vlo[rb + 4];
                mma16816(o[nt2], ah[0], ah[1], ah[2], ah[3], bh0, bh1);
                mma16816(o[nt2], ah[0], ah[1], ah[2], ah[3], bl0, bl1);
                mma16816(o[nt2], al[0], al[1], al[2], al[3], bh0, bh1);
            }
        }
        __syncthreads();
    }

    // Epilogue: normalize, write [B, S, H]
    float il0 = 1.f / l0r, il1 = 1.f / l1r;
    size_t base0 = ((size_t)b * SEQ + rA) * HID + h * HDIM;
    size_t base1 = base0 + (size_t)8 * HID;
#pragma unroll
    for (int nt = 0; nt < 8; nt++) {
        int d = nt * 8 + 2 * tig;
        *(float2*)&out[base0 + d] = make_float2(o[nt][0] * il0, o[nt][1] * il0);
        *(float2*)&out[base1 + d] = make_float2(o[nt][2] * il1, o[nt][3] * il1);
    }
}

// ---------------------------------------------------------------------------
extern "C" void kernel_launch(void* const* d_in, const int* in_sizes, int n_in,
                              void* d_out, int out_size)
{
    const float* hs   = (const float*)d_in[0];
    const float* mask = (const float*)d_in[1];
    const float* rel  = (const float*)d_in[2];
    const float* Wq   = (const float*)d_in[3];
    const float* bq   = (const float*)d_in[4];
    const float* Wk   = (const float*)d_in[5];
    const float* bk   = (const float*)d_in[6];
    const float* Wv   = (const float*)d_in[7];
    const float* bv   = (const float*)d_in[8];
    float* out = (float*)d_out;

    // Unconditional every call (no static guards — harness rule). Proven
    // capture-safe in round 0.
    cudaFuncSetAttribute(qkv_kernel,
        cudaFuncAttributeMaxDynamicSharedMemorySize, 8 * TSTRIDE * 4);
    cudaFuncSetAttribute(attn_kernel,
        cudaFuncAttributeMaxDynamicSharedMemorySize, 2 * ASTG * 4);

    split_kernel<<<XROWS, 128>>>(hs, Wq, Wk, Wv);

    dim3 g1(ROWS / 64, 24);
    qkv_kernel<<<g1, 128, 8 * TSTRIDE * 4>>>(bq, bk, bv);

    dim3 gv(SEQ / 64, BH);
    vtrans_kernel<<<gv, 256>>>();

    dim3 g2(SEQ / 64, BH);
    attn_kernel<<<g2, 128, 2 * ASTG * 4>>>(mask, rel, out);
}